// round 13
// baseline (speedup 1.0000x reference)
#include <cuda_runtime.h>
#include <math.h>
#include <stdint.h>

#define DD 512
#define KCLS 4
#define MP 8
#define JJ 32
#define INV_EPS 20.0f
#define GAMMA_M 0.999f
#define NMAX 200704
#define TOK 256                 // tokens per block
#define WSTRIDE 257             // Wt row stride in float2 (pad 1)
#define XSTRIDE 33              // Xs row stride in float2 (64 k = 32 f2 + 1 pad)
#define XS_BYTES (TOK * XSTRIDE * 8)          // 67584
#define WT_BYTES (JJ * WSTRIDE * 8)           // 65792
#define DSM_BYTES (XS_BYTES + WT_BYTES)

typedef unsigned long long ull;

// ---------------- device scratch (no allocations) ---------------------------
__device__ __align__(16) float gPN[JJ * DD];
__device__ __align__(16) float gS1[JJ];
__device__ __align__(16) float gS2[JJ];
__device__ __align__(16) float gCst[4];            // Q0, R0, B2
__device__ __align__(16) float gGG[DD];            // g^2
__device__ __align__(16) float gGB[DD];            // g*b
__device__ __align__(16) float2 gWt[JJ * WSTRIDE]; // (W[2kp][j], W[2kp+1][j])
__device__ __align__(16) float4 gABC[NMAX];
__device__ __align__(16) float gE[NMAX * MP];
__device__ unsigned char gPred[NMAX];
__device__ unsigned char gBucket[NMAX];
__device__ __align__(16) float gC[3][JJ];
__device__ __align__(16) float gBcnt[KCLS];
__device__ __align__(16) float gF[JJ * DD];
__device__ __align__(16) float gNcnt[JJ];

// ---------------- helpers ----------------------------------------------------
__device__ __forceinline__ void fma2(ull& acc, ull a, ull b) {
    asm("fma.rn.f32x2 %0, %1, %2, %0;" : "+l"(acc) : "l"(a), "l"(b));
}
__device__ __forceinline__ float fold2(ull v) {
    float lo, hi;
    asm("mov.b64 {%0, %1}, %2;" : "=f"(lo), "=f"(hi) : "l"(v));
    return lo + hi;
}

// ---------------- nop (profiler alignment: makes fused the 4th launch) -------
__global__ void nopKernel(int) {}

// ---------------- kernel 1: init ---------------------------------------------
__global__ void initKernel(const float* __restrict__ protos,
                           const float* __restrict__ g,
                           const float* __restrict__ b) {
    int tid = threadIdx.x;
    int w = tid >> 5, l = tid & 31;     // warp w handles prototype j = w

    for (int i = tid; i < JJ * DD; i += 1024) gF[i] = 0.f;
    if (tid < 3 * JJ) ((float*)gC)[tid] = 0.f;
    if (tid < JJ) gNcnt[tid] = 0.f;
    if (tid < KCLS) gBcnt[tid] = 0.f;
    if (tid < DD) { float gv = g[tid]; gGG[tid] = gv * gv; gGB[tid] = gv * b[tid]; }

    {   // prototype j = w: normalize, build Wt float2 k-pair image
        const float* p = protos + (size_t)w * DD;
        float v[16];
        float ss = 0.f;
#pragma unroll
        for (int i = 0; i < 8; i++) {
            int pr = l + 32 * i;
            v[2 * i]     = p[2 * pr];
            v[2 * i + 1] = p[2 * pr + 1];
            ss += v[2 * i] * v[2 * i] + v[2 * i + 1] * v[2 * i + 1];
        }
#pragma unroll
        for (int o = 16; o > 0; o >>= 1) ss += __shfl_xor_sync(0xffffffffu, ss, o);
        float inv = 1.f / fmaxf(sqrtf(ss), 1e-12f);
        float s1 = 0.f, s2 = 0.f;
#pragma unroll
        for (int i = 0; i < 8; i++) {
            int pr = l + 32 * i;
            int d0 = 2 * pr, d1 = d0 + 1;
            float pn0 = v[2 * i] * inv, pn1 = v[2 * i + 1] * inv;
            gPN[w * DD + d0] = pn0;
            gPN[w * DD + d1] = pn1;
            float g0 = g[d0], g1 = g[d1];
            s1 += g0 * pn0 + g1 * pn1;
            s2 += b[d0] * pn0 + b[d1] * pn1;
            gWt[w * WSTRIDE + pr] = make_float2(g0 * pn0, g1 * pn1);
        }
#pragma unroll
        for (int o = 16; o > 0; o >>= 1) {
            s1 += __shfl_xor_sync(0xffffffffu, s1, o);
            s2 += __shfl_xor_sync(0xffffffffu, s2, o);
        }
        if (l == 0) { gS1[w] = s1; gS2[w] = s2; }
    }

    if (w == 0) {
        float q0 = 0.f, r0 = 0.f, b2 = 0.f;
#pragma unroll
        for (int i = 0; i < 16; i++) {
            int d = l + 32 * i;
            float gv = g[d], bv = b[d];
            q0 += gv * gv; r0 += gv * bv; b2 += bv * bv;
        }
#pragma unroll
        for (int o = 16; o > 0; o >>= 1) {
            q0 += __shfl_xor_sync(0xffffffffu, q0, o);
            r0 += __shfl_xor_sync(0xffffffffu, r0, o);
            b2 += __shfl_xor_sync(0xffffffffu, b2, o);
        }
        if (l == 0) { gCst[0] = q0; gCst[1] = r0; gCst[2] = b2; gCst[3] = 0.f; }
    }
}

// ---------------- kernel 2: fused stats + FFMA2 GEMM + epilogue ---------------
__global__ void __launch_bounds__(256, 1)
fusedKernel(const float* __restrict__ X,
            const int* __restrict__ gt,
            const float* __restrict__ mg,
            const float* __restrict__ mb,
            float* __restrict__ outseg,
            int n) {
    extern __shared__ char dsm[];
    char* XsB = dsm;                       // Xs: TOK rows x 33 float2 (264 B/row)
    char* WtB = dsm + XS_BYTES;            // Wt: 32 rows x 257 float2 (2056 B/row)
    float* Msm = (float*)dsm;              // masks overlay [TOK][36] after GEMM
    __shared__ __align__(16) float sGG[DD], sGB[DD];
    __shared__ float4 sABS[TOK];
    __shared__ float sS1[JJ], sS2[JJ];
    __shared__ float sCp[8][JJ];
    __shared__ float sBp[KCLS];

    int tid = threadIdx.x;
    int tokBase = blockIdx.x * TOK;
    int tg = tid >> 3;                     // token group: rows tg*8 .. tg*8+7
    int jg = tid & 7;                      // col group:   cols jg*4 .. jg*4+3

    // stage Wt (65792 B) + gg/gb + small tables
    {
        const float4* src = (const float4*)gWt;
        float4* dst = (float4*)WtB;
        for (int i = tid; i < WT_BYTES / 16; i += 256) dst[i] = src[i];
    }
    for (int i = tid; i < DD; i += 256) { sGG[i] = gGG[i]; sGB[i] = gGB[i]; }
    if (tid < JJ) { sS1[tid] = gS1[tid]; sS2[tid] = gS2[tid]; }
    if (tid < 8 * JJ) ((float*)sCp)[tid] = 0.f;
    if (tid < KCLS) sBp[tid] = 0.f;

    int tok = tokBase + tid;               // staged row owned by this thread
    bool rowValid = tok < n;
    const float4* xr = (const float4*)(X + (size_t)(rowValid ? tok : 0) * DD);
    float2* myrow = (float2*)(XsB + tid * (XSTRIDE * 8));

    float sx = 0.f, sxx = 0.f, q2 = 0.f, q1 = 0.f, r1 = 0.f;

    // stage chunk 0 + its stats
    {
#pragma unroll
        for (int i = 0; i < 16; i++) {
            float4 v = rowValid ? xr[i] : make_float4(0.f, 0.f, 0.f, 0.f);
            float4 g4 = *(const float4*)(sGG + i * 4);
            float4 b4 = *(const float4*)(sGB + i * 4);
            float t;
            t = v.x * v.x; sx += v.x; sxx += t; q2 = fmaf(t, g4.x, q2); q1 = fmaf(v.x, g4.x, q1); r1 = fmaf(v.x, b4.x, r1);
            t = v.y * v.y; sx += v.y; sxx += t; q2 = fmaf(t, g4.y, q2); q1 = fmaf(v.y, g4.y, q1); r1 = fmaf(v.y, b4.y, r1);
            t = v.z * v.z; sx += v.z; sxx += t; q2 = fmaf(t, g4.z, q2); q1 = fmaf(v.z, g4.z, q1); r1 = fmaf(v.z, b4.z, r1);
            t = v.w * v.w; sx += v.w; sxx += t; q2 = fmaf(t, g4.w, q2); q1 = fmaf(v.w, g4.w, q1); r1 = fmaf(v.w, b4.w, r1);
            myrow[2 * i]     = make_float2(v.x, v.y);
            myrow[2 * i + 1] = make_float2(v.z, v.w);
        }
    }
    __syncthreads();

    ull acc[8][4];
#pragma unroll
    for (int i = 0; i < 8; i++)
#pragma unroll
        for (int c = 0; c < 4; c++) acc[i][c] = 0ull;

    const char* xrow0 = XsB + (tg * 8) * (XSTRIDE * 8);
    const char* wrow0 = WtB + (jg * 4) * (WSTRIDE * 8);

    for (int c8 = 0; c8 < 8; c8++) {
        // GEMM over 32 k-pairs of this chunk
        int kbyte = c8 * 32 * 8;
#pragma unroll 4
        for (int kp = 0; kp < 32; kp++) {
            ull w2[4];
#pragma unroll
            for (int c = 0; c < 4; c++)
                w2[c] = *(const ull*)(wrow0 + c * (WSTRIDE * 8) + kbyte + kp * 8);
#pragma unroll
            for (int i = 0; i < 8; i++) {
                ull x2 = *(const ull*)(xrow0 + i * (XSTRIDE * 8) + kp * 8);
#pragma unroll
                for (int c = 0; c < 4; c++) fma2(acc[i][c], x2, w2[c]);
            }
        }
        if (c8 < 7) {
            __syncthreads();
            int co = (c8 + 1) * 16;
#pragma unroll
            for (int i = 0; i < 16; i++) {
                float4 v = rowValid ? xr[co + i] : make_float4(0.f, 0.f, 0.f, 0.f);
                float4 g4 = *(const float4*)(sGG + (co + i) * 4);
                float4 b4 = *(const float4*)(sGB + (co + i) * 4);
                float t;
                t = v.x * v.x; sx += v.x; sxx += t; q2 = fmaf(t, g4.x, q2); q1 = fmaf(v.x, g4.x, q1); r1 = fmaf(v.x, b4.x, r1);
                t = v.y * v.y; sx += v.y; sxx += t; q2 = fmaf(t, g4.y, q2); q1 = fmaf(v.y, g4.y, q1); r1 = fmaf(v.y, b4.y, r1);
                t = v.z * v.z; sx += v.z; sxx += t; q2 = fmaf(t, g4.z, q2); q1 = fmaf(v.z, g4.z, q1); r1 = fmaf(v.z, b4.z, r1);
                t = v.w * v.w; sx += v.w; sxx += t; q2 = fmaf(t, g4.w, q2); q1 = fmaf(v.w, g4.w, q1); r1 = fmaf(v.w, b4.w, r1);
                myrow[2 * i]     = make_float2(v.x, v.y);
                myrow[2 * i + 1] = make_float2(v.z, v.w);
            }
            __syncthreads();
        }
    }

    // per-row LN/L2 coefficients (this thread owns row `tok` completely)
    {
        float Q0 = gCst[0], R0 = gCst[1], B2 = gCst[2];
        const float invD = 1.f / 512.f;
        float mu = sx * invD;
        float var = sxx * invD - mu * mu;
        float istd = rsqrtf(var + 1e-5f);
        float ysq = istd * istd * (q2 - 2.f * mu * q1 + mu * mu * Q0)
                  + 2.f * istd * (r1 - mu * R0) + B2;
        float inv = 1.f / fmaxf(sqrtf(fmaxf(ysq, 0.f)), 1e-12f);
        float4 abc = make_float4(istd * inv, -istd * mu * inv, inv, 0.f);
        sABS[tid] = abc;
        if (rowValid) gABC[tok] = abc;
    }

    __syncthreads();   // all GEMM LDS reads done -> overlay masks on Xs
#pragma unroll
    for (int i = 0; i < 8; i++)
#pragma unroll
        for (int c = 0; c < 4; c++)
            Msm[(tg * 8 + i) * 36 + jg * 4 + c] = fold2(acc[i][c]);
    __syncthreads();

    // epilogue: one thread per token
    if (rowValid) {
        float4 abc = sABS[tid];
        float m[32];
        float mx[4];
#pragma unroll
        for (int k = 0; k < 4; k++) {
            float best = -1e30f;
#pragma unroll
            for (int mm = 0; mm < 8; mm++) {
                int j = k * 8 + mm;
                float v = abc.x * Msm[tid * 36 + j] + abc.y * sS1[j] + abc.z * sS2[j];
                m[j] = v;
                best = fmaxf(best, v);
            }
            mx[k] = best;
        }
        float mu = 0.25f * (mx[0] + mx[1] + mx[2] + mx[3]);
        float var = 0.f;
#pragma unroll
        for (int k = 0; k < 4; k++) { float d = mx[k] - mu; var += d * d; }
        var *= 0.25f;
        float is4 = 1.f / sqrtf(var + 1e-5f);
        float o[4];
        int pred = 0; float bo = -1e30f;
#pragma unroll
        for (int k = 0; k < 4; k++) {
            o[k] = (mx[k] - mu) * is4 * mg[k] + mb[k];
            if (o[k] > bo) { bo = o[k]; pred = k; }
        }
        *(float4*)(outseg + (size_t)tok * 4) = make_float4(o[0], o[1], o[2], o[3]);
        gPred[tok] = (unsigned char)pred;

        int kk = gt[tok];
        float e[8];
#pragma unroll
        for (int mm = 0; mm < 8; mm++) e[mm] = expf(m[kk * 8 + mm] * INV_EPS);
        *(float4*)(gE + (size_t)tok * 8)     = make_float4(e[0], e[1], e[2], e[3]);
        *(float4*)(gE + (size_t)tok * 8 + 4) = make_float4(e[4], e[5], e[6], e[7]);
#pragma unroll
        for (int mm = 0; mm < 8; mm++)
            atomicAdd(&sCp[tid >> 5][kk * 8 + mm], e[mm]);
        atomicAdd(&sBp[kk], 1.f);
    }
    __syncthreads();
    if (tid < JJ) {
        float s = 0.f;
#pragma unroll
        for (int w = 0; w < 8; w++) s += sCp[w][tid];
        if (s != 0.f) atomicAdd(&gC[0][tid], s);
    }
    if (tid < KCLS && sBp[tid] != 0.f) atomicAdd(&gBcnt[tid], sBp[tid]);
}

// ---------------- kernel 3: one sinkhorn column iteration --------------------
__global__ void __launch_bounds__(256) sinkIterKernel(const int* __restrict__ gt,
                                                      int n, int src, int dst) {
    __shared__ float alpha[JJ];
    __shared__ float Cp[8][JJ];
    __shared__ float Bk[KCLS];
    int tid = threadIdx.x;
    int wrp = tid >> 5;
    if (tid < JJ) alpha[tid] = 1.f / fmaxf(8.f * gC[src][tid], 1e-30f);
    if (tid < 8 * JJ) ((float*)Cp)[tid] = 0.f;
    if (tid < KCLS) Bk[tid] = fmaxf(gBcnt[tid], 1.f);
    __syncthreads();

    int stride = gridDim.x * blockDim.x;
    for (int tok = blockIdx.x * blockDim.x + tid; tok < n; tok += stride) {
        int k = gt[tok];
        float4 a = *(const float4*)(gE + (size_t)tok * 8);
        float4 b4 = *(const float4*)(gE + (size_t)tok * 8 + 4);
        float e[8] = {a.x, a.y, a.z, a.w, b4.x, b4.y, b4.z, b4.w};
        float denom = 0.f;
#pragma unroll
        for (int mm = 0; mm < 8; mm++) denom += e[mm] * alpha[k * 8 + mm];
        float beta = 1.f / fmaxf(Bk[k] * denom, 1e-30f);
#pragma unroll
        for (int mm = 0; mm < 8; mm++) atomicAdd(&Cp[wrp][k * 8 + mm], e[mm] * beta);
    }
    __syncthreads();
    if (tid < JJ) {
        float s = 0.f;
#pragma unroll
        for (int w = 0; w < 8; w++) s += Cp[w][tid];
        if (s != 0.f) atomicAdd(&gC[dst][tid], s);
    }
}

// ---------------- kernel 4: bucket assignment --------------------------------
__global__ void __launch_bounds__(256) bucketKernel(const int* __restrict__ gt, int n) {
    __shared__ float invc[JJ];
    int tid = threadIdx.x;
    if (tid < JJ) invc[tid] = 1.f / fmaxf(gC[2][tid], 1e-30f);
    __syncthreads();
    int stride = gridDim.x * blockDim.x;
    for (int tok = blockIdx.x * blockDim.x + tid; tok < n; tok += stride) {
        int k = gt[tok];
        unsigned char bkt = 255;
        if (gPred[tok] == (unsigned char)k) {
            float4 a = *(const float4*)(gE + (size_t)tok * 8);
            float4 b4 = *(const float4*)(gE + (size_t)tok * 8 + 4);
            float e[8] = {a.x, a.y, a.z, a.w, b4.x, b4.y, b4.z, b4.w};
            float best = -1e30f; int bi = 0;
#pragma unroll
            for (int mm = 0; mm < 8; mm++) {
                float v = e[mm] * invc[k * 8 + mm];
                if (v > best) { best = v; bi = mm; }
            }
            bkt = (unsigned char)(k * 8 + bi);
        }
        gBucket[tok] = bkt;
    }
}

// ---------------- kernel 5: aggregation (register accumulators) --------------
#define AGG_SLICES 44
__global__ void __launch_bounds__(256) aggKernel(const float* __restrict__ X,
                                                 const float* __restrict__ g,
                                                 const float* __restrict__ b,
                                                 int n) {
    int l = threadIdx.x & 31;
    int wgid = blockIdx.x * 8 + (threadIdx.x >> 5);
    int bucket = wgid & 31;
    int slice = wgid >> 5;
    if (slice >= AGG_SLICES) return;

    int chunk = (n + AGG_SLICES - 1) / AGG_SLICES;
    int start = slice * chunk;
    int end = min(start + chunk, n);

    float gl[16], bl[16], acc[16];
#pragma unroll
    for (int i = 0; i < 16; i++) {
        gl[i] = g[l + 32 * i];
        bl[i] = b[l + 32 * i];
        acc[i] = 0.f;
    }
    int cnt = 0;

    for (int t0 = start; t0 < end; t0 += 32) {
        int tok = t0 + l;
        int myb = (tok < end) ? (int)gBucket[tok] : -1;
        unsigned mask = __ballot_sync(0xffffffffu, myb == bucket);
        cnt += __popc(mask);
        while (mask) {
            int bit = __ffs(mask) - 1;
            mask &= mask - 1;
            int th = t0 + bit;
            float4 abc = gABC[th];
            const float* x = X + (size_t)th * DD;
#pragma unroll
            for (int i = 0; i < 16; i++) {
                acc[i] += fmaf(abc.x * gl[i], x[l + 32 * i],
                               fmaf(abc.y, gl[i], abc.z * bl[i]));
            }
        }
    }
#pragma unroll
    for (int i = 0; i < 16; i++)
        if (acc[i] != 0.f) atomicAdd(&gF[bucket * DD + l + 32 * i], acc[i]);
    if (l == 0 && cnt > 0) atomicAdd(&gNcnt[bucket], (float)cnt);
}

// ---------------- kernel 6: finalize new prototypes ---------------------------
__global__ void finalKernel(float* __restrict__ outp) {
    int tid = threadIdx.x;
    int w = tid >> 5, l = tid & 31;
    int k = w >> 3;

    float nj = gNcnt[w];
    float nsum = 0.f;
#pragma unroll
    for (int mm = 0; mm < 8; mm++) nsum += gNcnt[k * 8 + mm];
    bool valid = (nj != 0.f) && (gBcnt[k] > 0.f) && (nsum > 0.f);

    float v[16];
    float ss = 0.f;
#pragma unroll
    for (int i = 0; i < 16; i++) {
        v[i] = gF[w * DD + l + 32 * i];
        ss += v[i] * v[i];
    }
#pragma unroll
    for (int o = 16; o > 0; o >>= 1) ss += __shfl_xor_sync(0xffffffffu, ss, o);
    float inv = 1.f / fmaxf(sqrtf(ss), 1e-12f);

    float out[16];
    float ss2 = 0.f;
#pragma unroll
    for (int i = 0; i < 16; i++) {
        float fn = v[i] * inv;
        float base = gPN[w * DD + l + 32 * i];
        float r = valid ? (GAMMA_M * base + (1.f - GAMMA_M) * fn) : base;
        out[i] = r;
        ss2 += r * r;
    }
#pragma unroll
    for (int o = 16; o > 0; o >>= 1) ss2 += __shfl_xor_sync(0xffffffffu, ss2, o);
    float inv2 = 1.f / fmaxf(sqrtf(ss2), 1e-12f);
#pragma unroll
    for (int i = 0; i < 16; i++)
        outp[w * DD + l + 32 * i] = out[i] * inv2;
}

// ---------------- launch ------------------------------------------------------
extern "C" void kernel_launch(void* const* d_in, const int* in_sizes, int n_in,
                              void* d_out, int out_size) {
    const float* feats  = (const float*)d_in[0];
    const float* ln_g   = (const float*)d_in[1];
    const float* ln_b   = (const float*)d_in[2];
    const float* mg     = (const float*)d_in[3];
    const float* mb     = (const float*)d_in[4];
    const float* protos = (const float*)d_in[5];
    const int*   gt     = (const int*)d_in[6];

    int n = in_sizes[0] / DD;
    float* outseg = (float*)d_out;
    float* outp   = (float*)d_out + (size_t)(out_size - JJ * DD);

    cudaFuncSetAttribute(fusedKernel, cudaFuncAttributeMaxDynamicSharedMemorySize, DSM_BYTES);

    initKernel<<<1, 1024>>>(protos, ln_g, ln_b);
    nopKernel<<<1, 32>>>(0);
    nopKernel<<<1, 32>>>(1);
    fusedKernel<<<(n + TOK - 1) / TOK, 256, DSM_BYTES>>>(feats, gt, mg, mb, outseg, n);
    sinkIterKernel<<<512, 256>>>(gt, n, 0, 1);
    sinkIterKernel<<<512, 256>>>(gt, n, 1, 2);
    bucketKernel<<<512, 256>>>(gt, n);
    aggKernel<<<(32 * AGG_SLICES + 7) / 8, 256>>>(feats, ln_g, ln_b, n);
    finalKernel<<<1, 1024>>>(outp);
}

// round 14
// speedup vs baseline: 1.2220x; 1.2220x over previous
#include <cuda_runtime.h>
#include <math.h>
#include <stdint.h>

#define DD 512
#define KCLS 4
#define MP 8
#define JJ 32
#define INV_EPS 20.0f
#define GAMMA_M 0.999f
#define NMAX 200704
#define TOK 256
#define XROW 272                        // bytes per X smem row (64 f32 + 16B pad)
#define WROW 272                        // bytes per W smem row (32 f2 + 16B pad)
#define XS_BYTES (TOK * XROW)           // 69632
#define WC_BYTES (32 * WROW)            // 8704
#define DSM_BYTES (XS_BYTES + WC_BYTES) // 78336

typedef unsigned long long ull;

// ---------------- device scratch (no allocations) ---------------------------
__device__ __align__(16) float gPN[JJ * DD];
__device__ __align__(16) float gS1[JJ];
__device__ __align__(16) float gS2[JJ];
__device__ __align__(16) float gCst[4];               // Q0, R0, B2
__device__ __align__(16) float gGG[DD];               // g^2
__device__ __align__(16) float gGB[DD];               // g*b
__device__ __align__(16) float2 gWc[8 * 32 * 32];     // [chunk][kp][j] = (W[2kp],W[2kp+1])
__device__ __align__(16) float4 gABC[NMAX];
__device__ __align__(16) float gE[NMAX * MP];
__device__ unsigned char gPred[NMAX];
__device__ unsigned char gBucket[NMAX];
__device__ __align__(16) float gC[3][JJ];
__device__ __align__(16) float gBcnt[KCLS];
__device__ __align__(16) float gF[JJ * DD];
__device__ __align__(16) float gNcnt[JJ];

// ---------------- helpers ----------------------------------------------------
__device__ __forceinline__ void fma2(ull& acc, ull a, ull b) {
    asm("fma.rn.f32x2 %0, %1, %2, %0;" : "+l"(acc) : "l"(a), "l"(b));
}
__device__ __forceinline__ float fold2(ull v) {
    float lo, hi;
    asm("mov.b64 {%0, %1}, %2;" : "=f"(lo), "=f"(hi) : "l"(v));
    return lo + hi;
}

__global__ void nopKernel(int) {}

// ---------------- kernel 1: init ---------------------------------------------
__global__ void initKernel(const float* __restrict__ protos,
                           const float* __restrict__ g,
                           const float* __restrict__ b) {
    int tid = threadIdx.x;
    int w = tid >> 5, l = tid & 31;     // warp w handles prototype j = w

    for (int i = tid; i < JJ * DD; i += 1024) gF[i] = 0.f;
    if (tid < 3 * JJ) ((float*)gC)[tid] = 0.f;
    if (tid < JJ) gNcnt[tid] = 0.f;
    if (tid < KCLS) gBcnt[tid] = 0.f;
    if (tid < DD) { float gv = g[tid]; gGG[tid] = gv * gv; gGB[tid] = gv * b[tid]; }

    {
        const float* p = protos + (size_t)w * DD;
        float v[16];
        float ss = 0.f;
#pragma unroll
        for (int i = 0; i < 8; i++) {
            int pr = l + 32 * i;
            v[2 * i]     = p[2 * pr];
            v[2 * i + 1] = p[2 * pr + 1];
            ss += v[2 * i] * v[2 * i] + v[2 * i + 1] * v[2 * i + 1];
        }
#pragma unroll
        for (int o = 16; o > 0; o >>= 1) ss += __shfl_xor_sync(0xffffffffu, ss, o);
        float inv = 1.f / fmaxf(sqrtf(ss), 1e-12f);
        float s1 = 0.f, s2 = 0.f;
#pragma unroll
        for (int i = 0; i < 8; i++) {
            int pr = l + 32 * i;          // global k-pair index 0..255
            int d0 = 2 * pr, d1 = d0 + 1;
            float pn0 = v[2 * i] * inv, pn1 = v[2 * i + 1] * inv;
            gPN[w * DD + d0] = pn0;
            gPN[w * DD + d1] = pn1;
            float g0 = g[d0], g1 = g[d1];
            s1 += g0 * pn0 + g1 * pn1;
            s2 += b[d0] * pn0 + b[d1] * pn1;
            int c = pr >> 5, kp = pr & 31;
            gWc[c * 1024 + kp * 32 + w] = make_float2(g0 * pn0, g1 * pn1);
        }
#pragma unroll
        for (int o = 16; o > 0; o >>= 1) {
            s1 += __shfl_xor_sync(0xffffffffu, s1, o);
            s2 += __shfl_xor_sync(0xffffffffu, s2, o);
        }
        if (l == 0) { gS1[w] = s1; gS2[w] = s2; }
    }

    if (w == 0) {
        float q0 = 0.f, r0 = 0.f, b2 = 0.f;
#pragma unroll
        for (int i = 0; i < 16; i++) {
            int d = l + 32 * i;
            float gv = g[d], bv = b[d];
            q0 += gv * gv; r0 += gv * bv; b2 += bv * bv;
        }
#pragma unroll
        for (int o = 16; o > 0; o >>= 1) {
            q0 += __shfl_xor_sync(0xffffffffu, q0, o);
            r0 += __shfl_xor_sync(0xffffffffu, r0, o);
            b2 += __shfl_xor_sync(0xffffffffu, b2, o);
        }
        if (l == 0) { gCst[0] = q0; gCst[1] = r0; gCst[2] = b2; gCst[3] = 0.f; }
    }
}

// ---------------- kernel 2: fused stats + FFMA2 GEMM + epilogue ---------------
__global__ void __launch_bounds__(256, 2)
fusedKernel(const float* __restrict__ X,
            const int* __restrict__ gt,
            const float* __restrict__ mg,
            const float* __restrict__ mb,
            float* __restrict__ outseg,
            int n) {
    extern __shared__ char dsm[];
    char* XsB = dsm;                      // X chunk: 256 rows x 272 B
    char* WcB = dsm + XS_BYTES;           // W chunk: 32 kp rows x 272 B
    float* Msm = (float*)dsm;             // masks overlay [256][36] after GEMM
    __shared__ __align__(16) float sGG[DD], sGB[DD];
    __shared__ float4 sABS[TOK];
    __shared__ float sS1[JJ], sS2[JJ];
    __shared__ float sCp[8][JJ];
    __shared__ float sBp[KCLS];

    int tid = threadIdx.x;
    int tokBase = blockIdx.x * TOK;
    int tg = tid >> 3;                    // thread's rows: tg + 32*i
    int jg = tid & 7;                     // thread's cols: jg*4 .. jg*4+3

    for (int i = tid; i < DD; i += 256) { sGG[i] = gGG[i]; sGB[i] = gGB[i]; }
    if (tid < JJ) { sS1[tid] = gS1[tid]; sS2[tid] = gS2[tid]; }
    if (tid < 8 * JJ) ((float*)sCp)[tid] = 0.f;
    if (tid < KCLS) sBp[tid] = 0.f;

    ull acc[8][4];
#pragma unroll
    for (int i = 0; i < 8; i++)
#pragma unroll
        for (int c = 0; c < 4; c++) acc[i][c] = 0ull;

    float sx = 0.f, sxx = 0.f, q2 = 0.f, q1 = 0.f, r1 = 0.f;

    const char* xp = XsB + tg * XROW;
    const char* wp = WcB + jg * 32;

    for (int c8 = 0; c8 < 8; c8++) {
        __syncthreads();   // previous chunk's reads complete
        // --- stage X chunk (coalesced: warp covers 2 full 256B row segments)
#pragma unroll
        for (int r = 0; r < 16; r++) {
            int li = r * 256 + tid;
            int row = li >> 4, col = li & 15;
            int tok = tokBase + row;
            float4 v = (tok < n)
                ? *(const float4*)(X + (size_t)tok * DD + c8 * 64 + col * 4)
                : make_float4(0.f, 0.f, 0.f, 0.f);
            *(float4*)(XsB + row * XROW + col * 16) = v;
        }
        // --- stage W chunk (8192 B = 512 float4)
        {
            const float4* src = (const float4*)gWc;
#pragma unroll
            for (int r = 0; r < 2; r++) {
                int li = r * 256 + tid;
                int kp = li >> 4, col = li & 15;
                *(float4*)(WcB + kp * WROW + col * 16) = src[c8 * 512 + li];
            }
        }
        __syncthreads();

        // --- stats for own row (reads smem, broadcast-cheap)
        {
            const float* myrow = (const float*)(XsB + tid * XROW);
            const float* ggc = sGG + c8 * 64;
            const float* gbc = sGB + c8 * 64;
#pragma unroll
            for (int i = 0; i < 16; i++) {
                float4 v = *(const float4*)(myrow + i * 4);
                float4 g4 = *(const float4*)(ggc + i * 4);
                float4 b4 = *(const float4*)(gbc + i * 4);
                float t;
                t = v.x * v.x; sx += v.x; sxx += t; q2 = fmaf(t, g4.x, q2); q1 = fmaf(v.x, g4.x, q1); r1 = fmaf(v.x, b4.x, r1);
                t = v.y * v.y; sx += v.y; sxx += t; q2 = fmaf(t, g4.y, q2); q1 = fmaf(v.y, g4.y, q1); r1 = fmaf(v.y, b4.y, r1);
                t = v.z * v.z; sx += v.z; sxx += t; q2 = fmaf(t, g4.z, q2); q1 = fmaf(v.z, g4.z, q1); r1 = fmaf(v.z, b4.z, r1);
                t = v.w * v.w; sx += v.w; sxx += t; q2 = fmaf(t, g4.w, q2); q1 = fmaf(v.w, g4.w, q1); r1 = fmaf(v.w, b4.w, r1);
            }
        }

        // --- GEMM: 16 iters x 2 k-pairs
#pragma unroll 4
        for (int kq = 0; kq < 16; kq++) {
            ulonglong2 wA  = *(const ulonglong2*)(wp + (2 * kq) * WROW);
            ulonglong2 wA2 = *(const ulonglong2*)(wp + (2 * kq) * WROW + 16);
            ulonglong2 wB  = *(const ulonglong2*)(wp + (2 * kq + 1) * WROW);
            ulonglong2 wB2 = *(const ulonglong2*)(wp + (2 * kq + 1) * WROW + 16);
#pragma unroll
            for (int i = 0; i < 8; i++) {
                ulonglong2 xv = *(const ulonglong2*)(xp + (32 * i) * XROW + kq * 16);
                fma2(acc[i][0], xv.x, wA.x);
                fma2(acc[i][1], xv.x, wA.y);
                fma2(acc[i][2], xv.x, wA2.x);
                fma2(acc[i][3], xv.x, wA2.y);
                fma2(acc[i][0], xv.y, wB.x);
                fma2(acc[i][1], xv.y, wB.y);
                fma2(acc[i][2], xv.y, wB2.x);
                fma2(acc[i][3], xv.y, wB2.y);
            }
        }
    }

    // per-row LN/L2 coefficients (thread owns row tokBase+tid)
    int tok = tokBase + tid;
    bool rowValid = tok < n;
    {
        float Q0 = gCst[0], R0 = gCst[1], B2 = gCst[2];
        const float invD = 1.f / 512.f;
        float mu = sx * invD;
        float var = sxx * invD - mu * mu;
        float istd = rsqrtf(var + 1e-5f);
        float ysq = istd * istd * (q2 - 2.f * mu * q1 + mu * mu * Q0)
                  + 2.f * istd * (r1 - mu * R0) + B2;
        float inv = 1.f / fmaxf(sqrtf(fmaxf(ysq, 0.f)), 1e-12f);
        float4 abc = make_float4(istd * inv, -istd * mu * inv, inv, 0.f);
        sABS[tid] = abc;
        if (rowValid) gABC[tok] = abc;
    }

    __syncthreads();   // GEMM reads done -> overlay masks
#pragma unroll
    for (int i = 0; i < 8; i++)
#pragma unroll
        for (int c = 0; c < 4; c++)
            Msm[(tg + 32 * i) * 36 + jg * 4 + c] = fold2(acc[i][c]);
    __syncthreads();

    // epilogue: one thread per token
    if (rowValid) {
        float4 abc = sABS[tid];
        float m[32];
        float mx[4];
#pragma unroll
        for (int k = 0; k < 4; k++) {
            float best = -1e30f;
#pragma unroll
            for (int mm = 0; mm < 8; mm++) {
                int j = k * 8 + mm;
                float v = abc.x * Msm[tid * 36 + j] + abc.y * sS1[j] + abc.z * sS2[j];
                m[j] = v;
                best = fmaxf(best, v);
            }
            mx[k] = best;
        }
        float mu = 0.25f * (mx[0] + mx[1] + mx[2] + mx[3]);
        float var = 0.f;
#pragma unroll
        for (int k = 0; k < 4; k++) { float d = mx[k] - mu; var += d * d; }
        var *= 0.25f;
        float is4 = 1.f / sqrtf(var + 1e-5f);
        float o[4];
        int pred = 0; float bo = -1e30f;
#pragma unroll
        for (int k = 0; k < 4; k++) {
            o[k] = (mx[k] - mu) * is4 * mg[k] + mb[k];
            if (o[k] > bo) { bo = o[k]; pred = k; }
        }
        *(float4*)(outseg + (size_t)tok * 4) = make_float4(o[0], o[1], o[2], o[3]);
        gPred[tok] = (unsigned char)pred;

        int kk = gt[tok];
        float e[8];
#pragma unroll
        for (int mm = 0; mm < 8; mm++) e[mm] = expf(m[kk * 8 + mm] * INV_EPS);
        *(float4*)(gE + (size_t)tok * 8)     = make_float4(e[0], e[1], e[2], e[3]);
        *(float4*)(gE + (size_t)tok * 8 + 4) = make_float4(e[4], e[5], e[6], e[7]);
#pragma unroll
        for (int mm = 0; mm < 8; mm++)
            atomicAdd(&sCp[tid >> 5][kk * 8 + mm], e[mm]);
        atomicAdd(&sBp[kk], 1.f);
    }
    __syncthreads();
    if (tid < JJ) {
        float s = 0.f;
#pragma unroll
        for (int w = 0; w < 8; w++) s += sCp[w][tid];
        if (s != 0.f) atomicAdd(&gC[0][tid], s);
    }
    if (tid < KCLS && sBp[tid] != 0.f) atomicAdd(&gBcnt[tid], sBp[tid]);
}

// ---------------- kernel 3: one sinkhorn column iteration --------------------
__global__ void __launch_bounds__(256) sinkIterKernel(const int* __restrict__ gt,
                                                      int n, int src, int dst) {
    __shared__ float alpha[JJ];
    __shared__ float Cp[8][JJ];
    __shared__ float Bk[KCLS];
    int tid = threadIdx.x;
    int wrp = tid >> 5;
    if (tid < JJ) alpha[tid] = 1.f / fmaxf(8.f * gC[src][tid], 1e-30f);
    if (tid < 8 * JJ) ((float*)Cp)[tid] = 0.f;
    if (tid < KCLS) Bk[tid] = fmaxf(gBcnt[tid], 1.f);
    __syncthreads();

    int stride = gridDim.x * blockDim.x;
    for (int tok = blockIdx.x * blockDim.x + tid; tok < n; tok += stride) {
        int k = gt[tok];
        float4 a = *(const float4*)(gE + (size_t)tok * 8);
        float4 b4 = *(const float4*)(gE + (size_t)tok * 8 + 4);
        float e[8] = {a.x, a.y, a.z, a.w, b4.x, b4.y, b4.z, b4.w};
        float denom = 0.f;
#pragma unroll
        for (int mm = 0; mm < 8; mm++) denom += e[mm] * alpha[k * 8 + mm];
        float beta = 1.f / fmaxf(Bk[k] * denom, 1e-30f);
#pragma unroll
        for (int mm = 0; mm < 8; mm++) atomicAdd(&Cp[wrp][k * 8 + mm], e[mm] * beta);
    }
    __syncthreads();
    if (tid < JJ) {
        float s = 0.f;
#pragma unroll
        for (int w = 0; w < 8; w++) s += Cp[w][tid];
        if (s != 0.f) atomicAdd(&gC[dst][tid], s);
    }
}

// ---------------- kernel 4: bucket assignment --------------------------------
__global__ void __launch_bounds__(256) bucketKernel(const int* __restrict__ gt, int n) {
    __shared__ float invc[JJ];
    int tid = threadIdx.x;
    if (tid < JJ) invc[tid] = 1.f / fmaxf(gC[2][tid], 1e-30f);
    __syncthreads();
    int stride = gridDim.x * blockDim.x;
    for (int tok = blockIdx.x * blockDim.x + tid; tok < n; tok += stride) {
        int k = gt[tok];
        unsigned char bkt = 255;
        if (gPred[tok] == (unsigned char)k) {
            float4 a = *(const float4*)(gE + (size_t)tok * 8);
            float4 b4 = *(const float4*)(gE + (size_t)tok * 8 + 4);
            float e[8] = {a.x, a.y, a.z, a.w, b4.x, b4.y, b4.z, b4.w};
            float best = -1e30f; int bi = 0;
#pragma unroll
            for (int mm = 0; mm < 8; mm++) {
                float v = e[mm] * invc[k * 8 + mm];
                if (v > best) { best = v; bi = mm; }
            }
            bkt = (unsigned char)(k * 8 + bi);
        }
        gBucket[tok] = bkt;
    }
}

// ---------------- kernel 5: aggregation (register accumulators) --------------
#define AGG_SLICES 44
__global__ void __launch_bounds__(256) aggKernel(const float* __restrict__ X,
                                                 const float* __restrict__ g,
                                                 const float* __restrict__ b,
                                                 int n) {
    int l = threadIdx.x & 31;
    int wgid = blockIdx.x * 8 + (threadIdx.x >> 5);
    int bucket = wgid & 31;
    int slice = wgid >> 5;
    if (slice >= AGG_SLICES) return;

    int chunk = (n + AGG_SLICES - 1) / AGG_SLICES;
    int start = slice * chunk;
    int end = min(start + chunk, n);

    float gl[16], bl[16], acc[16];
#pragma unroll
    for (int i = 0; i < 16; i++) {
        gl[i] = g[l + 32 * i];
        bl[i] = b[l + 32 * i];
        acc[i] = 0.f;
    }
    int cnt = 0;

    for (int t0 = start; t0 < end; t0 += 32) {
        int tok = t0 + l;
        int myb = (tok < end) ? (int)gBucket[tok] : -1;
        unsigned mask = __ballot_sync(0xffffffffu, myb == bucket);
        cnt += __popc(mask);
        while (mask) {
            int bit = __ffs(mask) - 1;
            mask &= mask - 1;
            int th = t0 + bit;
            float4 abc = gABC[th];
            const float* x = X + (size_t)th * DD;
#pragma unroll
            for (int i = 0; i < 16; i++) {
                acc[i] += fmaf(abc.x * gl[i], x[l + 32 * i],
                               fmaf(abc.y, gl[i], abc.z * bl[i]));
            }
        }
    }
#pragma unroll
    for (int i = 0; i < 16; i++)
        if (acc[i] != 0.f) atomicAdd(&gF[bucket * DD + l + 32 * i], acc[i]);
    if (l == 0 && cnt > 0) atomicAdd(&gNcnt[bucket], (float)cnt);
}

// ---------------- kernel 6: finalize new prototypes ---------------------------
__global__ void finalKernel(float* __restrict__ outp) {
    int tid = threadIdx.x;
    int w = tid >> 5, l = tid & 31;
    int k = w >> 3;

    float nj = gNcnt[w];
    float nsum = 0.f;
#pragma unroll
    for (int mm = 0; mm < 8; mm++) nsum += gNcnt[k * 8 + mm];
    bool valid = (nj != 0.f) && (gBcnt[k] > 0.f) && (nsum > 0.f);

    float v[16];
    float ss = 0.f;
#pragma unroll
    for (int i = 0; i < 16; i++) {
        v[i] = gF[w * DD + l + 32 * i];
        ss += v[i] * v[i];
    }
#pragma unroll
    for (int o = 16; o > 0; o >>= 1) ss += __shfl_xor_sync(0xffffffffu, ss, o);
    float inv = 1.f / fmaxf(sqrtf(ss), 1e-12f);

    float out[16];
    float ss2 = 0.f;
#pragma unroll
    for (int i = 0; i < 16; i++) {
        float fn = v[i] * inv;
        float base = gPN[w * DD + l + 32 * i];
        float r = valid ? (GAMMA_M * base + (1.f - GAMMA_M) * fn) : base;
        out[i] = r;
        ss2 += r * r;
    }
#pragma unroll
    for (int o = 16; o > 0; o >>= 1) ss2 += __shfl_xor_sync(0xffffffffu, ss2, o);
    float inv2 = 1.f / fmaxf(sqrtf(ss2), 1e-12f);
#pragma unroll
    for (int i = 0; i < 16; i++)
        outp[w * DD + l + 32 * i] = out[i] * inv2;
}

// ---------------- launch ------------------------------------------------------
extern "C" void kernel_launch(void* const* d_in, const int* in_sizes, int n_in,
                              void* d_out, int out_size) {
    const float* feats  = (const float*)d_in[0];
    const float* ln_g   = (const float*)d_in[1];
    const float* ln_b   = (const float*)d_in[2];
    const float* mg     = (const float*)d_in[3];
    const float* mb     = (const float*)d_in[4];
    const float* protos = (const float*)d_in[5];
    const int*   gt     = (const int*)d_in[6];

    int n = in_sizes[0] / DD;
    float* outseg = (float*)d_out;
    float* outp   = (float*)d_out + (size_t)(out_size - JJ * DD);

    cudaFuncSetAttribute(fusedKernel, cudaFuncAttributeMaxDynamicSharedMemorySize, DSM_BYTES);

    initKernel<<<1, 1024>>>(protos, ln_g, ln_b);
    nopKernel<<<1, 32>>>(0);
    nopKernel<<<1, 32>>>(1);
    fusedKernel<<<(n + TOK - 1) / TOK, 256, DSM_BYTES>>>(feats, gt, mg, mb, outseg, n);
    sinkIterKernel<<<512, 256>>>(gt, n, 0, 1);
    sinkIterKernel<<<512, 256>>>(gt, n, 1, 2);
    bucketKernel<<<512, 256>>>(gt, n);
    aggKernel<<<(32 * AGG_SLICES + 7) / 8, 256>>>(feats, ln_g, ln_b, n);
    finalKernel<<<1, 1024>>>(outp);
}